// round 13
// baseline (speedup 1.0000x reference)
#include <cuda_runtime.h>
#include <cuda_fp16.h>
#include <cstdint>

#define DH 128
#define BM 128
#define BN 128              // keys per pipeline stage (2 x 64-key sub-blocks)
#define NTHREADS 512
#define GRID_P 152          // 1 CTA/SM x 152 SMs -- exact residency

// smem (bytes): Q [128][128]h, K/V double-buffered 128-row tiles, mbarriers, ticket
#define SM_Q    0           // 32KB
#define SM_K0   32768       // 32KB
#define SM_V0   65536       // 32KB
#define SM_K1   98304       // 32KB
#define SM_V1   131072      // 32KB
#define SM_FULL 163840      // full[0], full[1] @ +0,+8
#define SM_FREE 163856      // free[0], free[1] @ +0,+8
#define SM_TILE 163872
#define SM_TOTAL 163888
// end-of-tile exchange regions (reuse stage-0 buffers after last read)
#define SM_XO   SM_K0       // 8 strips x 16 rows x 128 cols f32 = 64KB (K0+V0)
#define SM_XR   SM_Q        // 128 floats rowsum partials

#define MAXELEMS (32*2048*128)
__device__ __align__(16) __half g_kh[MAXELEMS];
__device__ __align__(16) __half g_vh[MAXELEMS];
__device__ unsigned int g_ticket;    // monotonic across launches
__device__ unsigned int g_arrive;    // monotonic across launches

__device__ __forceinline__ uint32_t smem_u32(const void* p) {
    uint32_t a;
    asm("{ .reg .u64 t; cvta.to.shared.u64 t, %1; cvt.u32.u64 %0, t; }" : "=r"(a) : "l"(p));
    return a;
}
__device__ __forceinline__ uint32_t pack2(float x, float y) {
    __half2 h = __floats2half2_rn(x, y);
    return *reinterpret_cast<uint32_t*>(&h);
}
__device__ __forceinline__ float ex2f(float x) {
    float y; asm("ex2.approx.f32 %0, %1;" : "=f"(y) : "f"(x)); return y;
}
__device__ __forceinline__ uint32_t ex2h2(uint32_t h2) {
    uint32_t y; asm("ex2.approx.f16x2 %0, %1;" : "=r"(y) : "r"(h2)); return y;
}
__device__ __forceinline__ void ldsm_x4(uint32_t* r, uint32_t addr) {
    asm volatile("ldmatrix.sync.aligned.m8n8.x4.shared.b16 {%0,%1,%2,%3}, [%4];"
                 : "=r"(r[0]), "=r"(r[1]), "=r"(r[2]), "=r"(r[3]) : "r"(addr));
}
__device__ __forceinline__ void ldsm_x4t(uint32_t* r, uint32_t addr) {
    asm volatile("ldmatrix.sync.aligned.m8n8.x4.trans.shared.b16 {%0,%1,%2,%3}, [%4];"
                 : "=r"(r[0]), "=r"(r[1]), "=r"(r[2]), "=r"(r[3]) : "r"(addr));
}
__device__ __forceinline__ void mma16816(float* c, const uint32_t* a, uint32_t b0, uint32_t b1) {
    asm volatile("mma.sync.aligned.m16n8k16.row.col.f32.f16.f16.f32 "
                 "{%0,%1,%2,%3},{%4,%5,%6,%7},{%8,%9},{%0,%1,%2,%3};"
                 : "+f"(c[0]), "+f"(c[1]), "+f"(c[2]), "+f"(c[3])
                 : "r"(a[0]), "r"(a[1]), "r"(a[2]), "r"(a[3]), "r"(b0), "r"(b1));
}
__device__ __forceinline__ void sts64(uint32_t addr, uint32_t a, uint32_t b) {
    asm volatile("st.shared.v2.b32 [%0], {%1,%2};" :: "r"(addr), "r"(a), "r"(b) : "memory");
}
__device__ __forceinline__ void sts64f(uint32_t addr, float a, float b) {
    asm volatile("st.shared.v2.b32 [%0], {%1,%2};" :: "r"(addr), "f"(a), "f"(b) : "memory");
}
__device__ __forceinline__ float2 lds64f(uint32_t addr) {
    float2 v;
    asm volatile("ld.shared.v2.b32 {%0,%1}, [%2];" : "=f"(v.x), "=f"(v.y) : "r"(addr));
    return v;
}
__device__ __forceinline__ void cpa16(uint32_t dst, const __half* src) {
    asm volatile("cp.async.cg.shared.global [%0], [%1], 16;"
                 :: "r"(dst), "l"(__cvta_generic_to_global(src)) : "memory");
}
#define CP_MBAR_ARRIVE(a) \
    asm volatile("cp.async.mbarrier.arrive.noinc.shared.b64 [%0];" :: "r"(a) : "memory")
#define MBAR_INIT(a, c) \
    asm volatile("mbarrier.init.shared.b64 [%0], %1;" :: "r"(a), "r"(c) : "memory")
#define MBAR_ARRIVE(a) \
    asm volatile("mbarrier.arrive.shared.b64 _, [%0];" :: "r"(a) : "memory")
#define MBAR_WAIT(addr, parity) do {                                                   \
    uint32_t _m = (addr), _p = (parity), _d;                                           \
    asm volatile("{.reg .pred p; mbarrier.try_wait.parity.acquire.cta.shared::cta.b64" \
                 " p, [%1], %2; selp.b32 %0,1,0,p;}"                                   \
                 : "=r"(_d) : "r"(_m), "r"(_p) : "memory");                            \
    if (!_d) {                                                                         \
        asm volatile("{.reg .pred P1;\n"                                               \
            "W_%=: mbarrier.try_wait.parity.acquire.cta.shared::cta.b64 P1,[%0],%1,0x989680;\n" \
            "@P1 bra.uni D_%=; bra.uni W_%=; D_%=:}\n"                                 \
            :: "r"(_m), "r"(_p) : "memory");                                           \
    }                                                                                  \
} while (0)

// 512 threads fill a 128x128(h) tile pair: thread = one row (tid>>2) x 4 chunks
__device__ __forceinline__ void issue_kv(uint32_t sbk, uint32_t sbv,
                                         const __half* kg, const __half* vg, int tid)
{
    const int row = tid >> 2;              // 0..127
    const int cg  = (tid & 3) * 4;         // chunk base 0,4,8,12
    const uint32_t rbase = row * 256;
    const uint32_t key   = (row & 7);
    const __half* ks = kg + row * DH + cg * 8;
    const __half* vs = vg + row * DH + cg * 8;
    #pragma unroll
    for (int c2 = 0; c2 < 4; c2++) {
        const uint32_t sw = rbase + (((cg + c2) ^ key) << 4);
        cpa16(sbk + sw, ks + c2 * 8);
        cpa16(sbv + sw, vs + c2 * 8);
    }
}

__global__ void __launch_bounds__(NTHREADS, 1)
attn_fused_kernel(const float* __restrict__ Q, const float* __restrict__ K,
                  const float* __restrict__ V, const int* __restrict__ lens,
                  float* __restrict__ O, int T, int nq, int ntiles, int total4)
{
    extern __shared__ __align__(1024) char smem[];
    const uint32_t sb = smem_u32(smem);
    volatile unsigned int* tslot = reinterpret_cast<unsigned int*>(smem + SM_TILE);

    const int tid  = threadIdx.x;
    const int lane = tid & 31;
    const int warp = tid >> 5;
    const int strip = warp & 7;          // row strip (16 rows)
    const int half  = warp >> 3;         // key half within each 64-key sub-block
    const int g = lane >> 2;
    const int r = lane & 3;

    // ===== phase 1: fp32 -> fp16 K/V, gated to ceil(L/128)*128 rows =====
    {
        const int rowsz = DH / 4;                       // 32 float4 per row
        for (int i = blockIdx.x * NTHREADS + tid; i < total4; i += GRID_P * NTHREADS) {
            const int b = i / (T * rowsz);
            const int t = (i / rowsz) % T;
            if (t < ((lens[b] + 127) & ~127)) {         // BN=128 rounding
                float4 k = reinterpret_cast<const float4*>(K)[i];
                float4 v = reinterpret_cast<const float4*>(V)[i];
                reinterpret_cast<uint2*>(g_kh)[i] = make_uint2(pack2(k.x, k.y), pack2(k.z, k.w));
                reinterpret_cast<uint2*>(g_vh)[i] = make_uint2(pack2(v.x, v.y), pack2(v.z, v.w));
            }
        }
    }

    // ===== grid barrier (monotonic, graph-replay-safe) =====
    __threadfence();
    __syncthreads();
    if (tid == 0) {
        unsigned a = atomicAdd(&g_arrive, 1u) + 1u;
        unsigned target = ((a + GRID_P - 1u) / GRID_P) * GRID_P;
        unsigned v;
        do {
            asm volatile("ld.acquire.gpu.u32 %0, [%1];" : "=r"(v) : "l"(&g_arrive) : "memory");
        } while (v < target);
        *tslot = target / GRID_P - 1u;                  // 0-based launch index
    }
    __syncthreads();
    const unsigned tbase = (*tslot) * (unsigned)(ntiles + GRID_P);

    // ===== phase 2: persistent attention =====
    const uint32_t la = lane & 7;
    const uint32_t ls = (lane >> 3) & 1;
    const uint32_t lc = lane >> 4;
    const uint32_t arow = strip * 16 + la + ls * 8;
    const uint32_t qbase_sm = sb + SM_Q + arow * 256;

    const float QSC = 1.4426950408889634f / 256.0f;   // log2e / (d/0.5)
    const uint32_t ONES = pack2(1.f, 1.f);

    for (;;) {
        __syncthreads();                 // all warps done with prev tile smem/barriers
        if (tid == 0) {
            *tslot = atomicAdd(&g_ticket, 1u) - tbase;
            MBAR_INIT(sb + SM_FULL + 0, NTHREADS);
            MBAR_INIT(sb + SM_FULL + 8, NTHREADS);
            MBAR_INIT(sb + SM_FREE + 0, NTHREADS);
            MBAR_INIT(sb + SM_FREE + 8, NTHREADS);
        }
        __syncthreads();
        const unsigned int t = *tslot;
        if (t >= (unsigned)ntiles) return;

        const int b     = (int)(t / (unsigned)nq);
        const int qbase = (int)(t % (unsigned)nq) * BM;
        const int L     = lens[b];
        float* Ob = O + ((size_t)b * T + qbase) * DH;

        if (L <= 0) {
            const float4 z = make_float4(0.f, 0.f, 0.f, 0.f);
            for (int i = tid; i < BM * DH / 4; i += NTHREADS)
                reinterpret_cast<float4*>(Ob)[i] = z;
            continue;
        }

        const int nblk = (L + BN - 1) >> 7;              // 128-key stages
        const __half* kg = g_kh + ((size_t)b * T) * DH;
        const __half* vg = g_vh + ((size_t)b * T) * DH;

        // prologue: fill stage 0 with block 0
        issue_kv(sb + SM_K0, sb + SM_V0, kg, vg, tid);
        CP_MBAR_ARRIVE(sb + SM_FULL + 0);

        // ---- Q tile: each warp stages 8 rows (strip*16 + half*8 + rr) ----
        const float* Qg = Q + ((size_t)b * T + qbase) * DH;
        {
            const uint32_t c   = lane >> 1;
            const uint32_t off = (lane & 1) * 8;
            #pragma unroll
            for (int rr = 0; rr < 8; rr++) {
                const int row = strip * 16 + half * 8 + rr;
                float4 v = reinterpret_cast<const float4*>(Qg + (size_t)row * DH)[lane];
                uint32_t a = sb + SM_Q + row * 256 + ((c ^ (row & 7)) << 4) + off;
                sts64(a, pack2(v.x * QSC, v.y * QSC), pack2(v.z * QSC, v.w * QSC));
            }
        }
        __syncthreads();                 // Q visible; keep producer convoyed (R9 lesson)

        float oacc[16][4];
        #pragma unroll
        for (int nt = 0; nt < 16; nt++)
            #pragma unroll
            for (int i = 0; i < 4; i++) oacc[nt][i] = 0.f;
        float rsum[4] = {0.f, 0.f, 0.f, 0.f};

        for (int kb = 0; kb < nblk; kb++) {
            const int s0 = kb & 1;
            const uint32_t kbuf = sb + (s0 ? SM_K1 : SM_K0);
            const uint32_t vbuf = sb + (s0 ? SM_V1 : SM_V0);

            if (kb + 1 < nblk) {
                const int s1 = s0 ^ 1;
                const int n = (kb + 1) >> 1;
                if (n > 0) MBAR_WAIT(sb + SM_FREE + s1 * 8, (n - 1) & 1);
                issue_kv(sb + (s1 ? SM_K1 : SM_K0), sb + (s1 ? SM_V1 : SM_V0),
                         kg + (size_t)(kb + 1) * BN * DH,
                         vg + (size_t)(kb + 1) * BN * DH, tid);
                CP_MBAR_ARRIVE(sb + SM_FULL + s1 * 8);
            }

            MBAR_WAIT(sb + SM_FULL + s0 * 8, (kb >> 1) & 1);

            // ---- two 64-key sub-blocks per stage ----
            #pragma unroll
            for (int sub = 0; sub < 2; sub++) {
                if (kb * BN + sub * 64 >= L) break;       // uniform: whole sub masked
                const uint32_t ksub = kbuf + sub * 16384; // 64 rows x 256B
                const uint32_t vsub = vbuf + sub * 16384;

                // ---- S = Q K^T : this warp's 16 rows x its 32 keys ----
                float sacc[4][4];
                #pragma unroll
                for (int nt = 0; nt < 4; nt++)
                    #pragma unroll
                    for (int i = 0; i < 4; i++) sacc[nt][i] = 0.f;

                #pragma unroll
                for (int kt = 0; kt < 8; kt++) {
                    const uint32_t xo = (((2 * kt + lc) ^ la) << 4);
                    uint32_t a[4];
                    ldsm_x4(a, qbase_sm + xo);
                    #pragma unroll
                    for (int ng = 0; ng < 2; ng++) {
                        uint32_t bb[4];
                        ldsm_x4(bb, ksub + (half * 32 + ng * 16 + la + ls * 8) * 256 + xo);
                        mma16816(sacc[ng * 2    ], a, bb[0], bb[2]);
                        mma16816(sacc[ng * 2 + 1], a, bb[1], bb[3]);
                    }
                }

                // ---- exp ----
                uint32_t pa[2][4];
                const int kcb = kb * BN + sub * 64 + half * 32;
                if (kcb + 32 <= L) {
                    #pragma unroll
                    for (int nt = 0; nt < 4; nt++) {
                        pa[nt >> 1][(nt & 1) * 2    ] = ex2h2(pack2(sacc[nt][0], sacc[nt][1]));
                        pa[nt >> 1][(nt & 1) * 2 + 1] = ex2h2(pack2(sacc[nt][2], sacc[nt][3]));
                    }
                } else {
                    #pragma unroll
                    for (int nt = 0; nt < 4; nt++) {
                        const int col = kcb + nt * 8 + 2 * r;
                        float p0 = (col     < L) ? ex2f(sacc[nt][0]) : 0.f;
                        float p1 = (col + 1 < L) ? ex2f(sacc[nt][1]) : 0.f;
                        float p2 = (col     < L) ? ex2f(sacc[nt][2]) : 0.f;
                        float p3 = (col + 1 < L) ? ex2f(sacc[nt][3]) : 0.f;
                        pa[nt >> 1][(nt & 1) * 2    ] = pack2(p0, p1);
                        pa[nt >> 1][(nt & 1) * 2 + 1] = pack2(p2, p3);
                    }
                }

                // ---- O += P V over this warp's 32 keys (full 128 output cols) ----
                #pragma unroll
                for (int kc = 0; kc < 2; kc++) {
                    mma16816(rsum, pa[kc], ONES, ONES);
                    const uint32_t vrow = (half * 32 + kc * 16 + la + ls * 8) * 256;
                    #pragma unroll
                    for (int ng = 0; ng < 8; ng++) {
                        uint32_t bb[4];
                        ldsm_x4t(bb, vsub + vrow + (((2 * ng + lc) ^ la) << 4));
                        mma16816(oacc[ng * 2    ], pa[kc], bb[0], bb[1]);
                        mma16816(oacc[ng * 2 + 1], pa[kc], bb[2], bb[3]);
                    }
                }
            }

            MBAR_ARRIVE(sb + SM_FREE + s0 * 8);
        }

        // ---- pair combine: half1 publishes partials, half0 merges + stores ----
        __syncthreads();                  // all reads of tile buffers done
        if (half == 1) {
            const uint32_t xo = sb + SM_XO + strip * 8192;
            #pragma unroll
            for (int nt = 0; nt < 16; nt++) {
                const uint32_t cb = nt * 32 + r * 8;
                sts64f(xo + g * 512 + cb,        oacc[nt][0], oacc[nt][1]);
                sts64f(xo + (g + 8) * 512 + cb,  oacc[nt][2], oacc[nt][3]);
            }
            if (r == 0) {
                *reinterpret_cast<float*>(smem + SM_XR + (strip * 16 + g) * 4)     = rsum[0];
                *reinterpret_cast<float*>(smem + SM_XR + (strip * 16 + 8 + g) * 4) = rsum[2];
            }
        }
        __syncthreads();
        if (half == 0) {
            const float* rsx = reinterpret_cast<const float*>(smem + SM_XR);
            const float inv0 = 1.0f / (rsum[0] + rsx[strip * 16 + g]);
            const float inv1 = 1.0f / (rsum[2] + rsx[strip * 16 + 8 + g]);
            const uint32_t xo = sb + SM_XO + strip * 8192;
            const int row0 = strip * 16 + g;
            #pragma unroll
            for (int nt = 0; nt < 16; nt++) {
                const int col = nt * 8 + 2 * r;
                const uint32_t cb = nt * 32 + r * 8;
                float2 x0 = lds64f(xo + g * 512 + cb);
                float2 x1 = lds64f(xo + (g + 8) * 512 + cb);
                *reinterpret_cast<float2*>(Ob + (size_t)row0 * DH + col) =
                    make_float2((oacc[nt][0] + x0.x) * inv0, (oacc[nt][1] + x0.y) * inv0);
                *reinterpret_cast<float2*>(Ob + (size_t)(row0 + 8) * DH + col) =
                    make_float2((oacc[nt][2] + x1.x) * inv1, (oacc[nt][3] + x1.y) * inv1);
            }
        }
    }
}

extern "C" void kernel_launch(void* const* d_in, const int* in_sizes, int n_in,
                              void* d_out, int out_size)
{
    const float* Q    = (const float*)d_in[0];
    const float* K    = (const float*)d_in[1];
    const float* V    = (const float*)d_in[2];
    const int*   lens = (const int*)d_in[3];
    float* O = (float*)d_out;

    const int B = in_sizes[3];
    const int T = in_sizes[0] / (B * DH);
    const int nq = T / BM;
    const int ntiles = nq * B;
    const int total4 = in_sizes[1] / 4;   // B*T*32 float4 per tensor

    cudaFuncSetAttribute(attn_fused_kernel,
                         cudaFuncAttributeMaxDynamicSharedMemorySize, SM_TOTAL);
    attn_fused_kernel<<<GRID_P, NTHREADS, SM_TOTAL>>>(Q, K, V, lens, O,
                                                      T, nq, ntiles, total4);
}

// round 14
// speedup vs baseline: 1.0722x; 1.0722x over previous
#include <cuda_runtime.h>
#include <cuda_fp16.h>
#include <cstdint>

#define DH 128
#define BM 128
#define BN 64
#define NTHREADS 512
#define GRID_P 152          // 1 CTA/SM x 152 SMs -- exact residency
#define NSTAGE 4

// smem (bytes): Q [128][128]h, 4-stage K/V ring, mbarriers, ticket
#define SM_Q    0           // 32KB
#define SM_ST   32768       // stage s: K @ +s*32768, V @ +s*32768+16384 (4 x 32KB)
#define SM_FULL 163840      // full[0..3] @ +0,8,16,24
#define SM_FREE 163872      // free[0..3]
#define SM_TILE 163904
#define SM_TOTAL 163920
// end-of-tile exchange regions (reuse stage 0/1 buffers after last read)
#define SM_XO   SM_ST       // 8 strips x 16 rows x 128 cols f32 = 64KB
#define SM_XR   SM_Q        // 128 floats rowsum partials

#define MAXELEMS (32*2048*128)
__device__ __align__(16) __half g_kh[MAXELEMS];
__device__ __align__(16) __half g_vh[MAXELEMS];
__device__ unsigned int g_ticket;    // monotonic across launches
__device__ unsigned int g_arrive;    // monotonic across launches

__device__ __forceinline__ uint32_t smem_u32(const void* p) {
    uint32_t a;
    asm("{ .reg .u64 t; cvta.to.shared.u64 t, %1; cvt.u32.u64 %0, t; }" : "=r"(a) : "l"(p));
    return a;
}
__device__ __forceinline__ uint32_t pack2(float x, float y) {
    __half2 h = __floats2half2_rn(x, y);
    return *reinterpret_cast<uint32_t*>(&h);
}
__device__ __forceinline__ float ex2f(float x) {
    float y; asm("ex2.approx.f32 %0, %1;" : "=f"(y) : "f"(x)); return y;
}
__device__ __forceinline__ uint32_t ex2h2(uint32_t h2) {
    uint32_t y; asm("ex2.approx.f16x2 %0, %1;" : "=r"(y) : "r"(h2)); return y;
}
__device__ __forceinline__ void ldsm_x4(uint32_t* r, uint32_t addr) {
    asm volatile("ldmatrix.sync.aligned.m8n8.x4.shared.b16 {%0,%1,%2,%3}, [%4];"
                 : "=r"(r[0]), "=r"(r[1]), "=r"(r[2]), "=r"(r[3]) : "r"(addr));
}
__device__ __forceinline__ void ldsm_x4t(uint32_t* r, uint32_t addr) {
    asm volatile("ldmatrix.sync.aligned.m8n8.x4.trans.shared.b16 {%0,%1,%2,%3}, [%4];"
                 : "=r"(r[0]), "=r"(r[1]), "=r"(r[2]), "=r"(r[3]) : "r"(addr));
}
__device__ __forceinline__ void mma16816(float* c, const uint32_t* a, uint32_t b0, uint32_t b1) {
    asm volatile("mma.sync.aligned.m16n8k16.row.col.f32.f16.f16.f32 "
                 "{%0,%1,%2,%3},{%4,%5,%6,%7},{%8,%9},{%0,%1,%2,%3};"
                 : "+f"(c[0]), "+f"(c[1]), "+f"(c[2]), "+f"(c[3])
                 : "r"(a[0]), "r"(a[1]), "r"(a[2]), "r"(a[3]), "r"(b0), "r"(b1));
}
__device__ __forceinline__ void sts64(uint32_t addr, uint32_t a, uint32_t b) {
    asm volatile("st.shared.v2.b32 [%0], {%1,%2};" :: "r"(addr), "r"(a), "r"(b) : "memory");
}
__device__ __forceinline__ void sts64f(uint32_t addr, float a, float b) {
    asm volatile("st.shared.v2.b32 [%0], {%1,%2};" :: "r"(addr), "f"(a), "f"(b) : "memory");
}
__device__ __forceinline__ float2 lds64f(uint32_t addr) {
    float2 v;
    asm volatile("ld.shared.v2.b32 {%0,%1}, [%2];" : "=f"(v.x), "=f"(v.y) : "r"(addr));
    return v;
}
__device__ __forceinline__ void cpa16(uint32_t dst, const __half* src) {
    asm volatile("cp.async.cg.shared.global [%0], [%1], 16;"
                 :: "r"(dst), "l"(__cvta_generic_to_global(src)) : "memory");
}
#define CP_MBAR_ARRIVE(a) \
    asm volatile("cp.async.mbarrier.arrive.noinc.shared.b64 [%0];" :: "r"(a) : "memory")
#define MBAR_INIT(a, c) \
    asm volatile("mbarrier.init.shared.b64 [%0], %1;" :: "r"(a), "r"(c) : "memory")
#define MBAR_ARRIVE(a) \
    asm volatile("mbarrier.arrive.shared.b64 _, [%0];" :: "r"(a) : "memory")
#define MBAR_WAIT(addr, parity) do {                                                   \
    uint32_t _m = (addr), _p = (parity), _d;                                           \
    asm volatile("{.reg .pred p; mbarrier.try_wait.parity.acquire.cta.shared::cta.b64" \
                 " p, [%1], %2; selp.b32 %0,1,0,p;}"                                   \
                 : "=r"(_d) : "r"(_m), "r"(_p) : "memory");                            \
    if (!_d) {                                                                         \
        asm volatile("{.reg .pred P1;\n"                                               \
            "W_%=: mbarrier.try_wait.parity.acquire.cta.shared::cta.b64 P1,[%0],%1,0x989680;\n" \
            "@P1 bra.uni D_%=; bra.uni W_%=; D_%=:}\n"                                 \
            :: "r"(_m), "r"(_p) : "memory");                                           \
    }                                                                                  \
} while (0)

// 512 threads fill a 64x128(h) K/V tile pair: thread = one row (tid>>3) x 2 chunks
__device__ __forceinline__ void issue_kv(uint32_t stage_base,
                                         const __half* kg, const __half* vg, int tid)
{
    const int row = tid >> 3;              // 0..63
    const int cg  = (tid & 7) * 2;         // chunk base
    const uint32_t rbase = row * 256;
    const uint32_t key   = (row & 7);
    const __half* ks = kg + row * DH + cg * 8;
    const __half* vs = vg + row * DH + cg * 8;
    #pragma unroll
    for (int c2 = 0; c2 < 2; c2++) {
        const uint32_t sw = rbase + (((cg + c2) ^ key) << 4);
        cpa16(stage_base + sw, ks + c2 * 8);            // K half of stage
        cpa16(stage_base + 16384 + sw, vs + c2 * 8);    // V half of stage
    }
}

__global__ void __launch_bounds__(NTHREADS, 1)
attn_fused_kernel(const float* __restrict__ Q, const float* __restrict__ K,
                  const float* __restrict__ V, const int* __restrict__ lens,
                  float* __restrict__ O, int T, int nq, int ntiles, int total4)
{
    extern __shared__ __align__(1024) char smem[];
    const uint32_t sb = smem_u32(smem);
    volatile unsigned int* tslot = reinterpret_cast<unsigned int*>(smem + SM_TILE);

    const int tid  = threadIdx.x;
    const int lane = tid & 31;
    const int warp = tid >> 5;
    const int strip = warp & 7;          // row strip (16 rows)
    const int half  = warp >> 3;         // key half (32 of 64 keys per block)
    const int g = lane >> 2;
    const int r = lane & 3;

    // ===== phase 1: fp32 -> fp16 K/V (length-gated to 64-row blocks) =====
    {
        const int rowsz = DH / 4;                       // 32 float4 per row
        for (int i = blockIdx.x * NTHREADS + tid; i < total4; i += GRID_P * NTHREADS) {
            const int b = i / (T * rowsz);
            const int t = (i / rowsz) % T;
            if (t < ((lens[b] + 63) & ~63)) {
                float4 k = reinterpret_cast<const float4*>(K)[i];
                float4 v = reinterpret_cast<const float4*>(V)[i];
                reinterpret_cast<uint2*>(g_kh)[i] = make_uint2(pack2(k.x, k.y), pack2(k.z, k.w));
                reinterpret_cast<uint2*>(g_vh)[i] = make_uint2(pack2(v.x, v.y), pack2(v.z, v.w));
            }
        }
    }

    // ===== grid barrier (monotonic, graph-replay-safe) =====
    __threadfence();
    __syncthreads();
    if (tid == 0) {
        unsigned a = atomicAdd(&g_arrive, 1u) + 1u;
        unsigned target = ((a + GRID_P - 1u) / GRID_P) * GRID_P;
        unsigned v;
        do {
            asm volatile("ld.acquire.gpu.u32 %0, [%1];" : "=r"(v) : "l"(&g_arrive) : "memory");
        } while (v < target);
        *tslot = target / GRID_P - 1u;                  // 0-based launch index
    }
    __syncthreads();
    const unsigned tbase = (*tslot) * (unsigned)(ntiles + GRID_P);

    // ===== phase 2: persistent attention =====
    const uint32_t la = lane & 7;
    const uint32_t ls = (lane >> 3) & 1;
    const uint32_t lc = lane >> 4;
    const uint32_t arow = strip * 16 + la + ls * 8;
    const uint32_t qbase_sm = sb + SM_Q + arow * 256;

    const float QSC = 1.4426950408889634f / 256.0f;   // log2e / (d/0.5)
    const uint32_t ONES = pack2(1.f, 1.f);

    for (;;) {
        __syncthreads();                 // all warps done with prev tile smem/barriers
        if (tid == 0) {
            *tslot = atomicAdd(&g_ticket, 1u) - tbase;
            #pragma unroll
            for (int s = 0; s < NSTAGE; s++) {
                MBAR_INIT(sb + SM_FULL + s * 8, NTHREADS);
                MBAR_INIT(sb + SM_FREE + s * 8, NTHREADS);
            }
        }
        __syncthreads();
        const unsigned int t = *tslot;
        if (t >= (unsigned)ntiles) return;

        const int b     = (int)(t / (unsigned)nq);
        const int qbase = (int)(t % (unsigned)nq) * BM;
        const int L     = lens[b];
        float* Ob = O + ((size_t)b * T + qbase) * DH;

        if (L <= 0) {
            const float4 z = make_float4(0.f, 0.f, 0.f, 0.f);
            for (int i = tid; i < BM * DH / 4; i += NTHREADS)
                reinterpret_cast<float4*>(Ob)[i] = z;
            continue;
        }

        const int nblk = (L + BN - 1) >> 6;
        const __half* kg = g_kh + ((size_t)b * T) * DH;
        const __half* vg = g_vh + ((size_t)b * T) * DH;

        // prologue: fill up to 3 stages ahead
        #pragma unroll
        for (int j = 0; j < NSTAGE - 1; j++) {
            if (j < nblk) {
                issue_kv(sb + SM_ST + j * 32768,
                         kg + (size_t)j * BN * DH, vg + (size_t)j * BN * DH, tid);
                CP_MBAR_ARRIVE(sb + SM_FULL + j * 8);
            }
        }

        // ---- Q tile: each warp stages 8 rows (strip*16 + half*8 + rr) ----
        const float* Qg = Q + ((size_t)b * T + qbase) * DH;
        {
            const uint32_t c   = lane >> 1;
            const uint32_t off = (lane & 1) * 8;
            #pragma unroll
            for (int rr = 0; rr < 8; rr++) {
                const int row = strip * 16 + half * 8 + rr;
                float4 v = reinterpret_cast<const float4*>(Qg + (size_t)row * DH)[lane];
                uint32_t a = sb + SM_Q + row * 256 + ((c ^ (row & 7)) << 4) + off;
                sts64(a, pack2(v.x * QSC, v.y * QSC), pack2(v.z * QSC, v.w * QSC));
            }
        }
        __syncthreads();                 // Q visible; keep producer convoyed (R9 lesson)

        float oacc[16][4];
        #pragma unroll
        for (int nt = 0; nt < 16; nt++)
            #pragma unroll
            for (int i = 0; i < 4; i++) oacc[nt][i] = 0.f;
        float rsum[4] = {0.f, 0.f, 0.f, 0.f};

        for (int kb = 0; kb < nblk; kb++) {
            const int s0 = kb & (NSTAGE - 1);
            const uint32_t kbuf = sb + SM_ST + s0 * 32768;
            const uint32_t vbuf = kbuf + 16384;

            // prefetch block kb+3 into its ring slot (deep lookahead)
            {
                const int j = kb + NSTAGE - 1;
                if (j < nblk) {
                    const int s1 = j & (NSTAGE - 1);
                    const int n = j >> 2;                // fill index of stage s1
                    if (n > 0) MBAR_WAIT(sb + SM_FREE + s1 * 8, (n - 1) & 1);
                    issue_kv(sb + SM_ST + s1 * 32768,
                             kg + (size_t)j * BN * DH, vg + (size_t)j * BN * DH, tid);
                    CP_MBAR_ARRIVE(sb + SM_FULL + s1 * 8);
                }
            }

            MBAR_WAIT(sb + SM_FULL + s0 * 8, (kb >> 2) & 1);

            // ---- S = Q K^T : this warp's 16 rows x its 32 keys ----
            float sacc[4][4];
            #pragma unroll
            for (int nt = 0; nt < 4; nt++)
                #pragma unroll
                for (int i = 0; i < 4; i++) sacc[nt][i] = 0.f;

            #pragma unroll
            for (int kt = 0; kt < 8; kt++) {
                const uint32_t xo = (((2 * kt + lc) ^ la) << 4);
                uint32_t a[4];
                ldsm_x4(a, qbase_sm + xo);
                #pragma unroll
                for (int ng = 0; ng < 2; ng++) {
                    uint32_t bb[4];
                    ldsm_x4(bb, kbuf + (half * 32 + ng * 16 + la + ls * 8) * 256 + xo);
                    mma16816(sacc[ng * 2    ], a, bb[0], bb[2]);
                    mma16816(sacc[ng * 2 + 1], a, bb[1], bb[3]);
                }
            }

            // ---- exp ----
            uint32_t pa[2][4];
            const int kcb = kb * BN + half * 32;
            if (kcb + 32 <= L) {
                #pragma unroll
                for (int nt = 0; nt < 4; nt++) {
                    pa[nt >> 1][(nt & 1) * 2    ] = ex2h2(pack2(sacc[nt][0], sacc[nt][1]));
                    pa[nt >> 1][(nt & 1) * 2 + 1] = ex2h2(pack2(sacc[nt][2], sacc[nt][3]));
                }
            } else {
                #pragma unroll
                for (int nt = 0; nt < 4; nt++) {
                    const int col = kcb + nt * 8 + 2 * r;
                    float p0 = (col     < L) ? ex2f(sacc[nt][0]) : 0.f;
                    float p1 = (col + 1 < L) ? ex2f(sacc[nt][1]) : 0.f;
                    float p2 = (col     < L) ? ex2f(sacc[nt][2]) : 0.f;
                    float p3 = (col + 1 < L) ? ex2f(sacc[nt][3]) : 0.f;
                    pa[nt >> 1][(nt & 1) * 2    ] = pack2(p0, p1);
                    pa[nt >> 1][(nt & 1) * 2 + 1] = pack2(p2, p3);
                }
            }

            // ---- O += P V over this warp's 32 keys (full 128 output cols) ----
            #pragma unroll
            for (int kc = 0; kc < 2; kc++) {
                mma16816(rsum, pa[kc], ONES, ONES);
                const uint32_t vrow = (half * 32 + kc * 16 + la + ls * 8) * 256;
                #pragma unroll
                for (int ng = 0; ng < 8; ng++) {
                    uint32_t bb[4];
                    ldsm_x4t(bb, vbuf + vrow + (((2 * ng + lc) ^ la) << 4));
                    mma16816(oacc[ng * 2    ], pa[kc], bb[0], bb[1]);
                    mma16816(oacc[ng * 2 + 1], pa[kc], bb[2], bb[3]);
                }
            }

            MBAR_ARRIVE(sb + SM_FREE + s0 * 8);
        }

        // ---- pair combine: half1 publishes partials, half0 merges + stores ----
        __syncthreads();                  // all reads of ring buffers done
        if (half == 1) {
            const uint32_t xo = sb + SM_XO + strip * 8192;
            #pragma unroll
            for (int nt = 0; nt < 16; nt++) {
                const uint32_t cb = nt * 32 + r * 8;
                sts64f(xo + g * 512 + cb,        oacc[nt][0], oacc[nt][1]);
                sts64f(xo + (g + 8) * 512 + cb,  oacc[nt][2], oacc[nt][3]);
            }
            if (r == 0) {
                *reinterpret_cast<float*>(smem + SM_XR + (strip * 16 + g) * 4)     = rsum[0];
                *reinterpret_cast<float*>(smem + SM_XR + (strip * 16 + 8 + g) * 4) = rsum[2];
            }
        }
        __syncthreads();
        if (half == 0) {
            const float* rsx = reinterpret_cast<const float*>(smem + SM_XR);
            const float inv0 = 1.0f / (rsum[0] + rsx[strip * 16 + g]);
            const float inv1 = 1.0f / (rsum[2] + rsx[strip * 16 + 8 + g]);
            const uint32_t xo = sb + SM_XO + strip * 8192;
            const int row0 = strip * 16 + g;
            #pragma unroll
            for (int nt = 0; nt < 16; nt++) {
                const int col = nt * 8 + 2 * r;
                const uint32_t cb = nt * 32 + r * 8;
                float2 x0 = lds64f(xo + g * 512 + cb);
                float2 x1 = lds64f(xo + (g + 8) * 512 + cb);
                *reinterpret_cast<float2*>(Ob + (size_t)row0 * DH + col) =
                    make_float2((oacc[nt][0] + x0.x) * inv0, (oacc[nt][1] + x0.y) * inv0);
                *reinterpret_cast<float2*>(Ob + (size_t)(row0 + 8) * DH + col) =
                    make_float2((oacc[nt][2] + x1.x) * inv1, (oacc[nt][3] + x1.y) * inv1);
            }
        }
    }
}

extern "C" void kernel_launch(void* const* d_in, const int* in_sizes, int n_in,
                              void* d_out, int out_size)
{
    const float* Q    = (const float*)d_in[0];
    const float* K    = (const float*)d_in[1];
    const float* V    = (const float*)d_in[2];
    const int*   lens = (const int*)d_in[3];
    float* O = (float*)d_out;

    const int B = in_sizes[3];
    const int T = in_sizes[0] / (B * DH);
    const int nq = T / BM;
    const int ntiles = nq * B;
    const int total4 = in_sizes[1] / 4;   // B*T*32 float4 per tensor

    cudaFuncSetAttribute(attn_fused_kernel,
                         cudaFuncAttributeMaxDynamicSharedMemorySize, SM_TOTAL);
    attn_fused_kernel<<<GRID_P, NTHREADS, SM_TOTAL>>>(Q, K, V, lens, O,
                                                      T, nq, ntiles, total4);
}

// round 15
// speedup vs baseline: 1.1126x; 1.0377x over previous
#include <cuda_runtime.h>
#include <cuda_fp16.h>
#include <cstdint>

#define DH 128
#define BM 128
#define BN 64
#define NTHREADS 512
#define GRID_P 152          // 1 CTA/SM x 152 SMs -- exact residency

// smem (bytes): Q [128][128]h, K/V double-buffered, mbarriers, ticket
#define SM_Q    0
#define SM_K0   32768
#define SM_V0   49152
#define SM_K1   65536
#define SM_V1   81920
#define SM_FULL 98304       // full[0], full[1] @ +0,+8
#define SM_FREE 98320       // free[0], free[1] @ +0,+8
#define SM_TILE 98336
#define SM_TOTAL 98352
// end-of-tile exchange regions (reuse tile buffers after last read)
#define SM_XO   SM_K0       // 8 strips x 16 rows x 128 cols f32 = 64KB
#define SM_XR   SM_Q        // 128 floats rowsum partials

#define MAXELEMS (32*2048*128)
__device__ __align__(16) __half g_kh[MAXELEMS];
__device__ __align__(16) __half g_vh[MAXELEMS];
__device__ unsigned int g_ticket;    // monotonic across launches
__device__ unsigned int g_arrive;    // monotonic across launches

__device__ __forceinline__ uint32_t smem_u32(const void* p) {
    uint32_t a;
    asm("{ .reg .u64 t; cvta.to.shared.u64 t, %1; cvt.u32.u64 %0, t; }" : "=r"(a) : "l"(p));
    return a;
}
__device__ __forceinline__ uint32_t pack2(float x, float y) {
    __half2 h = __floats2half2_rn(x, y);
    return *reinterpret_cast<uint32_t*>(&h);
}
__device__ __forceinline__ float ex2f(float x) {
    float y; asm("ex2.approx.f32 %0, %1;" : "=f"(y) : "f"(x)); return y;
}
__device__ __forceinline__ uint32_t ex2h2(uint32_t h2) {
    uint32_t y; asm("ex2.approx.f16x2 %0, %1;" : "=r"(y) : "r"(h2)); return y;
}
__device__ __forceinline__ void ldsm_x4(uint32_t* r, uint32_t addr) {
    asm volatile("ldmatrix.sync.aligned.m8n8.x4.shared.b16 {%0,%1,%2,%3}, [%4];"
                 : "=r"(r[0]), "=r"(r[1]), "=r"(r[2]), "=r"(r[3]) : "r"(addr));
}
__device__ __forceinline__ void ldsm_x4t(uint32_t* r, uint32_t addr) {
    asm volatile("ldmatrix.sync.aligned.m8n8.x4.trans.shared.b16 {%0,%1,%2,%3}, [%4];"
                 : "=r"(r[0]), "=r"(r[1]), "=r"(r[2]), "=r"(r[3]) : "r"(addr));
}
__device__ __forceinline__ void mma16816(float* c, const uint32_t* a, uint32_t b0, uint32_t b1) {
    asm volatile("mma.sync.aligned.m16n8k16.row.col.f32.f16.f16.f32 "
                 "{%0,%1,%2,%3},{%4,%5,%6,%7},{%8,%9},{%0,%1,%2,%3};"
                 : "+f"(c[0]), "+f"(c[1]), "+f"(c[2]), "+f"(c[3])
                 : "r"(a[0]), "r"(a[1]), "r"(a[2]), "r"(a[3]), "r"(b0), "r"(b1));
}
__device__ __forceinline__ void sts64(uint32_t addr, uint32_t a, uint32_t b) {
    asm volatile("st.shared.v2.b32 [%0], {%1,%2};" :: "r"(addr), "r"(a), "r"(b) : "memory");
}
__device__ __forceinline__ void sts64f(uint32_t addr, float a, float b) {
    asm volatile("st.shared.v2.b32 [%0], {%1,%2};" :: "r"(addr), "f"(a), "f"(b) : "memory");
}
__device__ __forceinline__ float2 lds64f(uint32_t addr) {
    float2 v;
    asm volatile("ld.shared.v2.b32 {%0,%1}, [%2];" : "=f"(v.x), "=f"(v.y) : "r"(addr));
    return v;
}
__device__ __forceinline__ void cpa16(uint32_t dst, const __half* src) {
    asm volatile("cp.async.cg.shared.global [%0], [%1], 16;"
                 :: "r"(dst), "l"(__cvta_generic_to_global(src)) : "memory");
}
__device__ __forceinline__ int ldg_nc(const int* p) {
    int v; asm volatile("ld.global.nc.s32 %0, [%1];" : "=r"(v) : "l"(p)); return v;
}
#define CP_MBAR_ARRIVE(a) \
    asm volatile("cp.async.mbarrier.arrive.noinc.shared.b64 [%0];" :: "r"(a) : "memory")
#define MBAR_INIT(a, c) \
    asm volatile("mbarrier.init.shared.b64 [%0], %1;" :: "r"(a), "r"(c) : "memory")
#define MBAR_ARRIVE(a) \
    asm volatile("mbarrier.arrive.shared.b64 _, [%0];" :: "r"(a) : "memory")
// consumer wait: acquire (orders subsequent generic smem reads)
#define MBAR_WAIT(addr, parity) do {                                                   \
    uint32_t _m = (addr), _p = (parity), _d;                                           \
    asm volatile("{.reg .pred p; mbarrier.try_wait.parity.acquire.cta.shared::cta.b64" \
                 " p, [%1], %2; selp.b32 %0,1,0,p;}"                                   \
                 : "=r"(_d) : "r"(_m), "r"(_p) : "memory");                            \
    if (!_d) {                                                                         \
        asm volatile("{.reg .pred P1;\n"                                               \
            "W_%=: mbarrier.try_wait.parity.acquire.cta.shared::cta.b64 P1,[%0],%1,0x989680;\n" \
            "@P1 bra.uni D_%=; bra.uni W_%=; D_%=:}\n"                                 \
            :: "r"(_m), "r"(_p) : "memory");                                           \
    }                                                                                  \
} while (0)
// producer wait: relaxed -- post-wait accesses are async-proxy (cp.async) only
#define MBAR_WAIT_RELAXED(addr, parity) do {                                           \
    uint32_t _m = (addr), _p = (parity), _d;                                           \
    asm volatile("{.reg .pred p; mbarrier.try_wait.parity.relaxed.cta.shared::cta.b64" \
                 " p, [%1], %2; selp.b32 %0,1,0,p;}"                                   \
                 : "=r"(_d) : "r"(_m), "r"(_p) : "memory");                            \
    if (!_d) {                                                                         \
        asm volatile("{.reg .pred P1;\n"                                               \
            "W_%=: mbarrier.try_wait.parity.relaxed.cta.shared::cta.b64 P1,[%0],%1,0x989680;\n" \
            "@P1 bra.uni D_%=; bra.uni W_%=; D_%=:}\n"                                 \
            :: "r"(_m), "r"(_p) : "memory");                                           \
    }                                                                                  \
} while (0)

// 512 threads fill a 64x128(h) K/V tile pair: thread = one row (tid>>3) x 2 chunks
__device__ __forceinline__ void issue_kv(uint32_t sbk, uint32_t sbv,
                                         const __half* kg, const __half* vg, int tid)
{
    const int row = tid >> 3;
    const int cg  = (tid & 7) * 2;
    const uint32_t rbase = row * 256;
    const uint32_t key   = (row & 7);
    const __half* ks = kg + row * DH + cg * 8;
    const __half* vs = vg + row * DH + cg * 8;
    #pragma unroll
    for (int c2 = 0; c2 < 2; c2++) {
        const uint32_t sw = rbase + (((cg + c2) ^ key) << 4);
        cpa16(sbk + sw, ks + c2 * 8);
        cpa16(sbv + sw, vs + c2 * 8);
    }
}

__global__ void __launch_bounds__(NTHREADS, 1)
attn_fused_kernel(const float* __restrict__ Q, const float* __restrict__ K,
                  const float* __restrict__ V, const int* __restrict__ lens,
                  float* __restrict__ O, int T, int nq, int ntiles, int total4)
{
    extern __shared__ __align__(1024) char smem[];
    const uint32_t sb = smem_u32(smem);
    volatile unsigned int* tslot = reinterpret_cast<unsigned int*>(smem + SM_TILE);

    const int tid  = threadIdx.x;
    const int lane = tid & 31;
    const int warp = tid >> 5;
    const int strip = warp & 7;          // row strip (16 rows)
    const int half  = warp >> 3;         // key half (32 of 64 keys per block)
    const int g = lane >> 2;
    const int r = lane & 3;

    // ===== phase 1: fp32 -> fp16 K/V (length-gated) =====
    {
        const int rowsz = DH / 4;                       // 32 float4 per row
        for (int i = blockIdx.x * NTHREADS + tid; i < total4; i += GRID_P * NTHREADS) {
            const int b = i / (T * rowsz);
            const int t = (i / rowsz) % T;
            if (t < ((ldg_nc(lens + b) + 63) & ~63)) {
                float4 k = reinterpret_cast<const float4*>(K)[i];
                float4 v = reinterpret_cast<const float4*>(V)[i];
                reinterpret_cast<uint2*>(g_kh)[i] = make_uint2(pack2(k.x, k.y), pack2(k.z, k.w));
                reinterpret_cast<uint2*>(g_vh)[i] = make_uint2(pack2(v.x, v.y), pack2(v.z, v.w));
            }
        }
    }

    // ===== grid barrier (monotonic, graph-replay-safe) =====
    __threadfence();
    __syncthreads();
    if (tid == 0) {
        unsigned a = atomicAdd(&g_arrive, 1u) + 1u;
        unsigned target = ((a + GRID_P - 1u) / GRID_P) * GRID_P;
        unsigned v;
        do {
            asm volatile("ld.acquire.gpu.u32 %0, [%1];" : "=r"(v) : "l"(&g_arrive) : "memory");
        } while (v < target);
        *tslot = target / GRID_P - 1u;                  // 0-based launch index
    }
    __syncthreads();
    const unsigned tbase = (*tslot) * (unsigned)(ntiles + GRID_P);

    // ===== phase 2: persistent attention (R12 structure) =====
    const uint32_t la = lane & 7;
    const uint32_t ls = (lane >> 3) & 1;
    const uint32_t lc = lane >> 4;
    const uint32_t arow = strip * 16 + la + ls * 8;
    const uint32_t qbase_sm = sb + SM_Q + arow * 256;

    const float QSC = 1.4426950408889634f / 256.0f;   // log2e / (d/0.5)
    const uint32_t ONES = pack2(1.f, 1.f);

    for (;;) {
        __syncthreads();                 // all warps done with prev tile smem/barriers
        if (tid == 0) {
            *tslot = atomicAdd(&g_ticket, 1u) - tbase;
            MBAR_INIT(sb + SM_FULL + 0, NTHREADS);
            MBAR_INIT(sb + SM_FULL + 8, NTHREADS);
            MBAR_INIT(sb + SM_FREE + 0, NTHREADS);
            MBAR_INIT(sb + SM_FREE + 8, NTHREADS);
        }
        __syncthreads();
        const unsigned int t = *tslot;
        if (t >= (unsigned)ntiles) return;

        const int b     = (int)(t / (unsigned)nq);
        const int qbase = (int)(t % (unsigned)nq) * BM;
        const int L     = ldg_nc(lens + b);
        float* Ob = O + ((size_t)b * T + qbase) * DH;

        if (L <= 0) {
            const float4 z = make_float4(0.f, 0.f, 0.f, 0.f);
            for (int i = tid; i < BM * DH / 4; i += NTHREADS)
                reinterpret_cast<float4*>(Ob)[i] = z;
            continue;
        }

        const int nblk = (L + BN - 1) >> 6;
        const __half* kg = g_kh + ((size_t)b * T) * DH;
        const __half* vg = g_vh + ((size_t)b * T) * DH;

        // prologue: fill stage 0 with block 0
        issue_kv(sb + SM_K0, sb + SM_V0, kg, vg, tid);
        CP_MBAR_ARRIVE(sb + SM_FULL + 0);

        // ---- Q tile: each warp stages 8 rows (strip*16 + half*8 + rr) ----
        const float* Qg = Q + ((size_t)b * T + qbase) * DH;
        {
            const uint32_t c   = lane >> 1;
            const uint32_t off = (lane & 1) * 8;
            #pragma unroll
            for (int rr = 0; rr < 8; rr++) {
                const int row = strip * 16 + half * 8 + rr;
                float4 v = reinterpret_cast<const float4*>(Qg + (size_t)row * DH)[lane];
                uint32_t a = sb + SM_Q + row * 256 + ((c ^ (row & 7)) << 4) + off;
                sts64(a, pack2(v.x * QSC, v.y * QSC), pack2(v.z * QSC, v.w * QSC));
            }
        }
        __syncthreads();                 // Q visible; keep producer convoyed (R9 lesson)

        float oacc[16][4];
        #pragma unroll
        for (int nt = 0; nt < 16; nt++)
            #pragma unroll
            for (int i = 0; i < 4; i++) oacc[nt][i] = 0.f;
        float rsum[4] = {0.f, 0.f, 0.f, 0.f};

        for (int kb = 0; kb < nblk; kb++) {
            const int s0 = kb & 1;
            const uint32_t kbuf = sb + (s0 ? SM_K1 : SM_K0);
            const uint32_t vbuf = sb + (s0 ? SM_V1 : SM_V0);

            if (kb + 1 < nblk) {
                const int s1 = s0 ^ 1;
                const int n = (kb + 1) >> 1;
                if (n > 0) MBAR_WAIT_RELAXED(sb + SM_FREE + s1 * 8, (n - 1) & 1);
                issue_kv(sb + (s1 ? SM_K1 : SM_K0), sb + (s1 ? SM_V1 : SM_V0),
                         kg + (size_t)(kb + 1) * BN * DH,
                         vg + (size_t)(kb + 1) * BN * DH, tid);
                CP_MBAR_ARRIVE(sb + SM_FULL + s1 * 8);
            }

            MBAR_WAIT(sb + SM_FULL + s0 * 8, (kb >> 1) & 1);

            // ---- S = Q K^T : this warp's 16 rows x its 32 keys ----
            float sacc[4][4];
            #pragma unroll
            for (int nt = 0; nt < 4; nt++)
                #pragma unroll
                for (int i = 0; i < 4; i++) sacc[nt][i] = 0.f;

            #pragma unroll
            for (int kt = 0; kt < 8; kt++) {
                const uint32_t xo = (((2 * kt + lc) ^ la) << 4);
                uint32_t a[4];
                ldsm_x4(a, qbase_sm + xo);
                #pragma unroll
                for (int ng = 0; ng < 2; ng++) {
                    uint32_t bb[4];
                    ldsm_x4(bb, kbuf + (half * 32 + ng * 16 + la + ls * 8) * 256 + xo);
                    mma16816(sacc[ng * 2    ], a, bb[0], bb[2]);
                    mma16816(sacc[ng * 2 + 1], a, bb[1], bb[3]);
                }
            }

            // ---- exp ----
            uint32_t pa[2][4];
            const int kcb = kb * BN + half * 32;
            if (kcb + 32 <= L) {
                #pragma unroll
                for (int nt = 0; nt < 4; nt++) {
                    pa[nt >> 1][(nt & 1) * 2    ] = ex2h2(pack2(sacc[nt][0], sacc[nt][1]));
                    pa[nt >> 1][(nt & 1) * 2 + 1] = ex2h2(pack2(sacc[nt][2], sacc[nt][3]));
                }
            } else {
                #pragma unroll
                for (int nt = 0; nt < 4; nt++) {
                    const int col = kcb + nt * 8 + 2 * r;
                    float p0 = (col     < L) ? ex2f(sacc[nt][0]) : 0.f;
                    float p1 = (col + 1 < L) ? ex2f(sacc[nt][1]) : 0.f;
                    float p2 = (col     < L) ? ex2f(sacc[nt][2]) : 0.f;
                    float p3 = (col + 1 < L) ? ex2f(sacc[nt][3]) : 0.f;
                    pa[nt >> 1][(nt & 1) * 2    ] = pack2(p0, p1);
                    pa[nt >> 1][(nt & 1) * 2 + 1] = pack2(p2, p3);
                }
            }

            // ---- O += P V over this warp's 32 keys (full 128 output cols) ----
            #pragma unroll
            for (int kc = 0; kc < 2; kc++) {
                mma16816(rsum, pa[kc], ONES, ONES);
                const uint32_t vrow = (half * 32 + kc * 16 + la + ls * 8) * 256;
                #pragma unroll
                for (int ng = 0; ng < 8; ng++) {
                    uint32_t bb[4];
                    ldsm_x4t(bb, vbuf + vrow + (((2 * ng + lc) ^ la) << 4));
                    mma16816(oacc[ng * 2    ], pa[kc], bb[0], bb[1]);
                    mma16816(oacc[ng * 2 + 1], pa[kc], bb[2], bb[3]);
                }
            }

            MBAR_ARRIVE(sb + SM_FREE + s0 * 8);
        }

        // ---- pair combine: half1 publishes partials, half0 merges + stores ----
        __syncthreads();                  // all reads of tile buffers done
        if (half == 1) {
            const uint32_t xo = sb + SM_XO + strip * 8192;
            #pragma unroll
            for (int nt = 0; nt < 16; nt++) {
                const uint32_t cb = nt * 32 + r * 8;
                sts64f(xo + g * 512 + cb,        oacc[nt][0], oacc[nt][1]);
                sts64f(xo + (g + 8) * 512 + cb,  oacc[nt][2], oacc[nt][3]);
            }
            if (r == 0) {
                *reinterpret_cast<float*>(smem + SM_XR + (strip * 16 + g) * 4)     = rsum[0];
                *reinterpret_cast<float*>(smem + SM_XR + (strip * 16 + 8 + g) * 4) = rsum[2];
            }
        }
        __syncthreads();
        if (half == 0) {
            const float* rsx = reinterpret_cast<const float*>(smem + SM_XR);
            const float inv0 = 1.0f / (rsum[0] + rsx[strip * 16 + g]);
            const float inv1 = 1.0f / (rsum[2] + rsx[strip * 16 + 8 + g]);
            const uint32_t xo = sb + SM_XO + strip * 8192;
            const int row0 = strip * 16 + g;
            #pragma unroll
            for (int nt = 0; nt < 16; nt++) {
                const int col = nt * 8 + 2 * r;
                const uint32_t cb = nt * 32 + r * 8;
                float2 x0 = lds64f(xo + g * 512 + cb);
                float2 x1 = lds64f(xo + (g + 8) * 512 + cb);
                *reinterpret_cast<float2*>(Ob + (size_t)row0 * DH + col) =
                    make_float2((oacc[nt][0] + x0.x) * inv0, (oacc[nt][1] + x0.y) * inv0);
                *reinterpret_cast<float2*>(Ob + (size_t)(row0 + 8) * DH + col) =
                    make_float2((oacc[nt][2] + x1.x) * inv1, (oacc[nt][3] + x1.y) * inv1);
            }
        }
    }
}

extern "C" void kernel_launch(void* const* d_in, const int* in_sizes, int n_in,
                              void* d_out, int out_size)
{
    const float* Q    = (const float*)d_in[0];
    const float* K    = (const float*)d_in[1];
    const float* V    = (const float*)d_in[2];
    const int*   lens = (const int*)d_in[3];
    float* O = (float*)d_out;

    const int B = in_sizes[3];
    const int T = in_sizes[0] / (B * DH);
    const int nq = T / BM;
    const int ntiles = nq * B;
    const int total4 = in_sizes[1] / 4;   // B*T*32 float4 per tensor

    cudaFuncSetAttribute(attn_fused_kernel,
                         cudaFuncAttributeMaxDynamicSharedMemorySize, SM_TOTAL);
    attn_fused_kernel<<<GRID_P, NTHREADS, SM_TOTAL>>>(Q, K, V, lens, O,
                                                      T, nq, ntiles, total4);
}

// round 16
// speedup vs baseline: 1.2819x; 1.1522x over previous
#include <cuda_runtime.h>
#include <cuda_fp16.h>
#include <cstdint>

#define DH 128
#define BM 128
#define BN 64
#define NTHREADS 512
#define GRID_P 152          // 1 CTA/SM x 152 SMs -- exact residency

// smem (bytes): Q [128][128]h, K/V double-buffered, mbarriers, ticket, LPT order
#define SM_Q    0
#define SM_K0   32768
#define SM_V0   49152
#define SM_K1   65536
#define SM_V1   81920
#define SM_FULL 98304       // full[0], full[1] @ +0,+8
#define SM_FREE 98320       // free[0], free[1] @ +0,+8
#define SM_TILE 98336
#define SM_ORD  98352       // up to 64 batch indices, LPT-sorted
#define SM_TOTAL 98608
// end-of-tile exchange regions (reuse tile buffers after last read)
#define SM_XO   SM_K0       // 8 strips x 16 rows x 128 cols f32 = 64KB
#define SM_XR   SM_Q        // 128 floats rowsum partials

#define MAXELEMS (32*2048*128)
__device__ __align__(16) __half g_kh[MAXELEMS];
__device__ __align__(16) __half g_vh[MAXELEMS];
__device__ unsigned int g_ticket;    // monotonic across launches
__device__ unsigned int g_arrive;    // monotonic across launches

__device__ __forceinline__ uint32_t smem_u32(const void* p) {
    uint32_t a;
    asm("{ .reg .u64 t; cvta.to.shared.u64 t, %1; cvt.u32.u64 %0, t; }" : "=r"(a) : "l"(p));
    return a;
}
__device__ __forceinline__ uint32_t pack2(float x, float y) {
    __half2 h = __floats2half2_rn(x, y);
    return *reinterpret_cast<uint32_t*>(&h);
}
__device__ __forceinline__ float ex2f(float x) {
    float y; asm("ex2.approx.f32 %0, %1;" : "=f"(y) : "f"(x)); return y;
}
__device__ __forceinline__ uint32_t ex2h2(uint32_t h2) {
    uint32_t y; asm("ex2.approx.f16x2 %0, %1;" : "=r"(y) : "r"(h2)); return y;
}
__device__ __forceinline__ void ldsm_x4(uint32_t* r, uint32_t addr) {
    asm volatile("ldmatrix.sync.aligned.m8n8.x4.shared.b16 {%0,%1,%2,%3}, [%4];"
                 : "=r"(r[0]), "=r"(r[1]), "=r"(r[2]), "=r"(r[3]) : "r"(addr));
}
__device__ __forceinline__ void ldsm_x4t(uint32_t* r, uint32_t addr) {
    asm volatile("ldmatrix.sync.aligned.m8n8.x4.trans.shared.b16 {%0,%1,%2,%3}, [%4];"
                 : "=r"(r[0]), "=r"(r[1]), "=r"(r[2]), "=r"(r[3]) : "r"(addr));
}
__device__ __forceinline__ void mma16816(float* c, const uint32_t* a, uint32_t b0, uint32_t b1) {
    asm volatile("mma.sync.aligned.m16n8k16.row.col.f32.f16.f16.f32 "
                 "{%0,%1,%2,%3},{%4,%5,%6,%7},{%8,%9},{%0,%1,%2,%3};"
                 : "+f"(c[0]), "+f"(c[1]), "+f"(c[2]), "+f"(c[3])
                 : "r"(a[0]), "r"(a[1]), "r"(a[2]), "r"(a[3]), "r"(b0), "r"(b1));
}
__device__ __forceinline__ void sts64(uint32_t addr, uint32_t a, uint32_t b) {
    asm volatile("st.shared.v2.b32 [%0], {%1,%2};" :: "r"(addr), "r"(a), "r"(b) : "memory");
}
__device__ __forceinline__ void sts64f(uint32_t addr, float a, float b) {
    asm volatile("st.shared.v2.b32 [%0], {%1,%2};" :: "r"(addr), "f"(a), "f"(b) : "memory");
}
__device__ __forceinline__ float2 lds64f(uint32_t addr) {
    float2 v;
    asm volatile("ld.shared.v2.b32 {%0,%1}, [%2];" : "=f"(v.x), "=f"(v.y) : "r"(addr));
    return v;
}
__device__ __forceinline__ void cpa16(uint32_t dst, const __half* src) {
    asm volatile("cp.async.cg.shared.global [%0], [%1], 16;"
                 :: "r"(dst), "l"(__cvta_generic_to_global(src)) : "memory");
}
#define CP_MBAR_ARRIVE(a) \
    asm volatile("cp.async.mbarrier.arrive.noinc.shared.b64 [%0];" :: "r"(a) : "memory")
#define MBAR_INIT(a, c) \
    asm volatile("mbarrier.init.shared.b64 [%0], %1;" :: "r"(a), "r"(c) : "memory")
#define MBAR_ARRIVE(a) \
    asm volatile("mbarrier.arrive.shared.b64 _, [%0];" :: "r"(a) : "memory")
#define MBAR_WAIT(addr, parity) do {                                                   \
    uint32_t _m = (addr), _p = (parity), _d;                                           \
    asm volatile("{.reg .pred p; mbarrier.try_wait.parity.acquire.cta.shared::cta.b64" \
                 " p, [%1], %2; selp.b32 %0,1,0,p;}"                                   \
                 : "=r"(_d) : "r"(_m), "r"(_p) : "memory");                            \
    if (!_d) {                                                                         \
        asm volatile("{.reg .pred P1;\n"                                               \
            "W_%=: mbarrier.try_wait.parity.acquire.cta.shared::cta.b64 P1,[%0],%1,0x989680;\n" \
            "@P1 bra.uni D_%=; bra.uni W_%=; D_%=:}\n"                                 \
            :: "r"(_m), "r"(_p) : "memory");                                           \
    }                                                                                  \
} while (0)

// 512 threads fill a 64x128(h) K/V tile pair: thread = one row (tid>>3) x 2 chunks
__device__ __forceinline__ void issue_kv(uint32_t sbk, uint32_t sbv,
                                         const __half* kg, const __half* vg, int tid)
{
    const int row = tid >> 3;
    const int cg  = (tid & 7) * 2;
    const uint32_t rbase = row * 256;
    const uint32_t key   = (row & 7);
    const __half* ks = kg + row * DH + cg * 8;
    const __half* vs = vg + row * DH + cg * 8;
    #pragma unroll
    for (int c2 = 0; c2 < 2; c2++) {
        const uint32_t sw = rbase + (((cg + c2) ^ key) << 4);
        cpa16(sbk + sw, ks + c2 * 8);
        cpa16(sbv + sw, vs + c2 * 8);
    }
}

__global__ void __launch_bounds__(NTHREADS, 1)
attn_fused_kernel(const float* __restrict__ Q, const float* __restrict__ K,
                  const float* __restrict__ V, const int* __restrict__ lens,
                  float* __restrict__ O, int T, int nq, int ntiles, int total4, int B)
{
    extern __shared__ __align__(1024) char smem[];
    const uint32_t sb = smem_u32(smem);
    volatile unsigned int* tslot = reinterpret_cast<unsigned int*>(smem + SM_TILE);
    int* ord = reinterpret_cast<int*>(smem + SM_ORD);

    const int tid  = threadIdx.x;
    const int lane = tid & 31;
    const int warp = tid >> 5;
    const int strip = warp & 7;          // row strip (16 rows)
    const int half  = warp >> 3;         // key half (32 of 64 keys per block)
    const int g = lane >> 2;
    const int r = lane & 3;

    // ===== phase 1: fp32 -> fp16 K/V (length-gated) =====
    {
        const int rowsz = DH / 4;                       // 32 float4 per row
        for (int i = blockIdx.x * NTHREADS + tid; i < total4; i += GRID_P * NTHREADS) {
            const int b = i / (T * rowsz);
            const int t = (i / rowsz) % T;
            if (t < ((lens[b] + 63) & ~63)) {
                float4 k = reinterpret_cast<const float4*>(K)[i];
                float4 v = reinterpret_cast<const float4*>(V)[i];
                reinterpret_cast<uint2*>(g_kh)[i] = make_uint2(pack2(k.x, k.y), pack2(k.z, k.w));
                reinterpret_cast<uint2*>(g_vh)[i] = make_uint2(pack2(v.x, v.y), pack2(v.z, v.w));
            }
        }
    }

    // ===== LPT order: rank batches by descending L (stable) =====
    if (tid < B && B <= 64) {
        const int Lb = lens[tid];
        int rank = 0;
        for (int j = 0; j < B; j++) {
            const int Lj = lens[j];
            rank += (Lj > Lb) || (Lj == Lb && j < tid);
        }
        ord[rank] = tid;
    } else if (tid < 64 && tid < B) {
        ord[tid] = tid;                   // fallback (unused for B<=64)
    }

    // ===== grid barrier (monotonic, graph-replay-safe) =====
    __threadfence();
    __syncthreads();
    if (tid == 0) {
        unsigned a = atomicAdd(&g_arrive, 1u) + 1u;
        unsigned target = ((a + GRID_P - 1u) / GRID_P) * GRID_P;
        unsigned v;
        do {
            asm volatile("ld.acquire.gpu.u32 %0, [%1];" : "=r"(v) : "l"(&g_arrive) : "memory");
        } while (v < target);
        *tslot = target / GRID_P - 1u;                  // 0-based launch index
    }
    __syncthreads();
    const unsigned tbase = (*tslot) * (unsigned)(ntiles + GRID_P);

    // ===== phase 2: persistent attention (R12 core) =====
    const uint32_t la = lane & 7;
    const uint32_t ls = (lane >> 3) & 1;
    const uint32_t lc = lane >> 4;
    const uint32_t arow = strip * 16 + la + ls * 8;
    const uint32_t qbase_sm = sb + SM_Q + arow * 256;

    const float QSC = 1.4426950408889634f / 256.0f;   // log2e / (d/0.5)
    const uint32_t ONES = pack2(1.f, 1.f);

    for (;;) {
        __syncthreads();                 // all warps done with prev tile smem/barriers
        if (tid == 0) {
            *tslot = atomicAdd(&g_ticket, 1u) - tbase;
            MBAR_INIT(sb + SM_FULL + 0, NTHREADS);
            MBAR_INIT(sb + SM_FULL + 8, NTHREADS);
            MBAR_INIT(sb + SM_FREE + 0, NTHREADS);
            MBAR_INIT(sb + SM_FREE + 8, NTHREADS);
        }
        __syncthreads();
        const unsigned int t = *tslot;
        if (t >= (unsigned)ntiles) return;

        const int b     = ord[t / (unsigned)nq];        // LPT: longest batches first
        const int qbase = (int)(t % (unsigned)nq) * BM;
        const int L     = lens[b];
        float* Ob = O + ((size_t)b * T + qbase) * DH;

        if (L <= 0) {
            const float4 z = make_float4(0.f, 0.f, 0.f, 0.f);
            for (int i = tid; i < BM * DH / 4; i += NTHREADS)
                reinterpret_cast<float4*>(Ob)[i] = z;
            continue;
        }

        const int nblk = (L + BN - 1) >> 6;
        const __half* kg = g_kh + ((size_t)b * T) * DH;
        const __half* vg = g_vh + ((size_t)b * T) * DH;

        // prologue: fill stage 0 with block 0
        issue_kv(sb + SM_K0, sb + SM_V0, kg, vg, tid);
        CP_MBAR_ARRIVE(sb + SM_FULL + 0);

        // ---- Q tile: each warp stages 8 rows (strip*16 + half*8 + rr) ----
        const float* Qg = Q + ((size_t)b * T + qbase) * DH;
        {
            const uint32_t c   = lane >> 1;
            const uint32_t off = (lane & 1) * 8;
            #pragma unroll
            for (int rr = 0; rr < 8; rr++) {
                const int row = strip * 16 + half * 8 + rr;
                float4 v = reinterpret_cast<const float4*>(Qg + (size_t)row * DH)[lane];
                uint32_t a = sb + SM_Q + row * 256 + ((c ^ (row & 7)) << 4) + off;
                sts64(a, pack2(v.x * QSC, v.y * QSC), pack2(v.z * QSC, v.w * QSC));
            }
        }
        __syncthreads();                 // Q visible; keep producer convoyed (R9 lesson)

        float oacc[16][4];
        #pragma unroll
        for (int nt = 0; nt < 16; nt++)
            #pragma unroll
            for (int i = 0; i < 4; i++) oacc[nt][i] = 0.f;
        float rsum[4] = {0.f, 0.f, 0.f, 0.f};

        for (int kb = 0; kb < nblk; kb++) {
            const int s0 = kb & 1;
            const uint32_t kbuf = sb + (s0 ? SM_K1 : SM_K0);
            const uint32_t vbuf = sb + (s0 ? SM_V1 : SM_V0);

            if (kb + 1 < nblk) {
                const int s1 = s0 ^ 1;
                const int n = (kb + 1) >> 1;
                if (n > 0) MBAR_WAIT(sb + SM_FREE + s1 * 8, (n - 1) & 1);
                issue_kv(sb + (s1 ? SM_K1 : SM_K0), sb + (s1 ? SM_V1 : SM_V0),
                         kg + (size_t)(kb + 1) * BN * DH,
                         vg + (size_t)(kb + 1) * BN * DH, tid);
                CP_MBAR_ARRIVE(sb + SM_FULL + s1 * 8);
            }

            MBAR_WAIT(sb + SM_FULL + s0 * 8, (kb >> 1) & 1);

            // ---- S = Q K^T : this warp's 16 rows x its 32 keys ----
            float sacc[4][4];
            #pragma unroll
            for (int nt = 0; nt < 4; nt++)
                #pragma unroll
                for (int i = 0; i < 4; i++) sacc[nt][i] = 0.f;

            #pragma unroll
            for (int kt = 0; kt < 8; kt++) {
                const uint32_t xo = (((2 * kt + lc) ^ la) << 4);
                uint32_t a[4];
                ldsm_x4(a, qbase_sm + xo);
                #pragma unroll
                for (int ng = 0; ng < 2; ng++) {
                    uint32_t bb[4];
                    ldsm_x4(bb, kbuf + (half * 32 + ng * 16 + la + ls * 8) * 256 + xo);
                    mma16816(sacc[ng * 2    ], a, bb[0], bb[2]);
                    mma16816(sacc[ng * 2 + 1], a, bb[1], bb[3]);
                }
            }

            // ---- exp ----
            uint32_t pa[2][4];
            const int kcb = kb * BN + half * 32;
            if (kcb + 32 <= L) {
                #pragma unroll
                for (int nt = 0; nt < 4; nt++) {
                    pa[nt >> 1][(nt & 1) * 2    ] = ex2h2(pack2(sacc[nt][0], sacc[nt][1]));
                    pa[nt >> 1][(nt & 1) * 2 + 1] = ex2h2(pack2(sacc[nt][2], sacc[nt][3]));
                }
            } else {
                #pragma unroll
                for (int nt = 0; nt < 4; nt++) {
                    const int col = kcb + nt * 8 + 2 * r;
                    float p0 = (col     < L) ? ex2f(sacc[nt][0]) : 0.f;
                    float p1 = (col + 1 < L) ? ex2f(sacc[nt][1]) : 0.f;
                    float p2 = (col     < L) ? ex2f(sacc[nt][2]) : 0.f;
                    float p3 = (col + 1 < L) ? ex2f(sacc[nt][3]) : 0.f;
                    pa[nt >> 1][(nt & 1) * 2    ] = pack2(p0, p1);
                    pa[nt >> 1][(nt & 1) * 2 + 1] = pack2(p2, p3);
                }
            }

            // ---- O += P V over this warp's 32 keys (full 128 output cols) ----
            #pragma unroll
            for (int kc = 0; kc < 2; kc++) {
                mma16816(rsum, pa[kc], ONES, ONES);
                const uint32_t vrow = (half * 32 + kc * 16 + la + ls * 8) * 256;
                #pragma unroll
                for (int ng = 0; ng < 8; ng++) {
                    uint32_t bb[4];
                    ldsm_x4t(bb, vbuf + vrow + (((2 * ng + lc) ^ la) << 4));
                    mma16816(oacc[ng * 2    ], pa[kc], bb[0], bb[1]);
                    mma16816(oacc[ng * 2 + 1], pa[kc], bb[2], bb[3]);
                }
            }

            MBAR_ARRIVE(sb + SM_FREE + s0 * 8);
        }

        // ---- pair combine: half1 publishes partials, half0 merges + stores ----
        __syncthreads();                  // all reads of tile buffers done
        if (half == 1) {
            const uint32_t xo = sb + SM_XO + strip * 8192;
            #pragma unroll
            for (int nt = 0; nt < 16; nt++) {
                const uint32_t cb = nt * 32 + r * 8;
                sts64f(xo + g * 512 + cb,        oacc[nt][0], oacc[nt][1]);
                sts64f(xo + (g + 8) * 512 + cb,  oacc[nt][2], oacc[nt][3]);
            }
            if (r == 0) {
                *reinterpret_cast<float*>(smem + SM_XR + (strip * 16 + g) * 4)     = rsum[0];
                *reinterpret_cast<float*>(smem + SM_XR + (strip * 16 + 8 + g) * 4) = rsum[2];
            }
        }
        __syncthreads();
        if (half == 0) {
            const float* rsx = reinterpret_cast<const float*>(smem + SM_XR);
            const float inv0 = 1.0f / (rsum[0] + rsx[strip * 16 + g]);
            const float inv1 = 1.0f / (rsum[2] + rsx[strip * 16 + 8 + g]);
            const uint32_t xo = sb + SM_XO + strip * 8192;
            const int row0 = strip * 16 + g;
            #pragma unroll
            for (int nt = 0; nt < 16; nt++) {
                const int col = nt * 8 + 2 * r;
                const uint32_t cb = nt * 32 + r * 8;
                float2 x0 = lds64f(xo + g * 512 + cb);
                float2 x1 = lds64f(xo + (g + 8) * 512 + cb);
                *reinterpret_cast<float2*>(Ob + (size_t)row0 * DH + col) =
                    make_float2((oacc[nt][0] + x0.x) * inv0, (oacc[nt][1] + x0.y) * inv0);
                *reinterpret_cast<float2*>(Ob + (size_t)(row0 + 8) * DH + col) =
                    make_float2((oacc[nt][2] + x1.x) * inv1, (oacc[nt][3] + x1.y) * inv1);
            }
        }
    }
}

extern "C" void kernel_launch(void* const* d_in, const int* in_sizes, int n_in,
                              void* d_out, int out_size)
{
    const float* Q    = (const float*)d_in[0];
    const float* K    = (const float*)d_in[1];
    const float* V    = (const float*)d_in[2];
    const int*   lens = (const int*)d_in[3];
    float* O = (float*)d_out;

    const int B = in_sizes[3];
    const int T = in_sizes[0] / (B * DH);
    const int nq = T / BM;
    const int ntiles = nq * B;
    const int total4 = in_sizes[1] / 4;   // B*T*32 float4 per tensor

    cudaFuncSetAttribute(attn_fused_kernel,
                         cudaFuncAttributeMaxDynamicSharedMemorySize, SM_TOTAL);
    attn_fused_kernel<<<GRID_P, NTHREADS, SM_TOTAL>>>(Q, K, V, lens, O,
                                                      T, nq, ntiles, total4, B);
}

// round 17
// speedup vs baseline: 1.2919x; 1.0078x over previous
#include <cuda_runtime.h>
#include <cuda_fp16.h>
#include <cstdint>

#define DH 128
#define BM 128
#define BN 64
#define NTHREADS 512
#define GRID_P 152          // 1 CTA/SM x 152 SMs -- exact residency

// smem (bytes): Q [128][128]h, K/V double-buffered, mbarriers, ticket, LPT order
#define SM_Q    0
#define SM_K0   32768
#define SM_V0   49152
#define SM_K1   65536
#define SM_V1   81920
#define SM_FULL 98304       // full[0], full[1] @ +0,+8
#define SM_FREE 98320       // free[0], free[1] @ +0,+8
#define SM_TILE 98336
#define SM_ORD  98352       // up to 64 batch indices, LPT-sorted
#define SM_TOTAL 98608
// end-of-tile exchange regions (reuse tile buffers after last read)
#define SM_XO   SM_K0       // 8 strips x 16 rows x 128 cols f32 = 64KB
#define SM_XR   SM_Q        // 128 floats rowsum partials

#define MAXELEMS (32*2048*128)
__device__ __align__(16) __half g_kh[MAXELEMS];
__device__ __align__(16) __half g_vh[MAXELEMS];
__device__ unsigned int g_ticket;    // monotonic across launches
__device__ unsigned int g_arrive;    // monotonic across launches

__device__ __forceinline__ uint32_t smem_u32(const void* p) {
    uint32_t a;
    asm("{ .reg .u64 t; cvta.to.shared.u64 t, %1; cvt.u32.u64 %0, t; }" : "=r"(a) : "l"(p));
    return a;
}
__device__ __forceinline__ uint32_t pack2(float x, float y) {
    __half2 h = __floats2half2_rn(x, y);
    return *reinterpret_cast<uint32_t*>(&h);
}
__device__ __forceinline__ float ex2f(float x) {
    float y; asm("ex2.approx.f32 %0, %1;" : "=f"(y) : "f"(x)); return y;
}
__device__ __forceinline__ uint32_t ex2h2(uint32_t h2) {
    uint32_t y; asm("ex2.approx.f16x2 %0, %1;" : "=r"(y) : "r"(h2)); return y;
}
__device__ __forceinline__ void ldsm_x4(uint32_t* r, uint32_t addr) {
    asm volatile("ldmatrix.sync.aligned.m8n8.x4.shared.b16 {%0,%1,%2,%3}, [%4];"
                 : "=r"(r[0]), "=r"(r[1]), "=r"(r[2]), "=r"(r[3]) : "r"(addr));
}
__device__ __forceinline__ void ldsm_x4t(uint32_t* r, uint32_t addr) {
    asm volatile("ldmatrix.sync.aligned.m8n8.x4.trans.shared.b16 {%0,%1,%2,%3}, [%4];"
                 : "=r"(r[0]), "=r"(r[1]), "=r"(r[2]), "=r"(r[3]) : "r"(addr));
}
// NOTE: non-volatile -- pure register semantics; lets ptxas interleave HMMAs
// with ex2/LDSM streams (register deps enforce correctness).
__device__ __forceinline__ void mma16816(float* c, const uint32_t* a, uint32_t b0, uint32_t b1) {
    asm("mma.sync.aligned.m16n8k16.row.col.f32.f16.f16.f32 "
        "{%0,%1,%2,%3},{%4,%5,%6,%7},{%8,%9},{%0,%1,%2,%3};"
        : "+f"(c[0]), "+f"(c[1]), "+f"(c[2]), "+f"(c[3])
        : "r"(a[0]), "r"(a[1]), "r"(a[2]), "r"(a[3]), "r"(b0), "r"(b1));
}
__device__ __forceinline__ void sts64(uint32_t addr, uint32_t a, uint32_t b) {
    asm volatile("st.shared.v2.b32 [%0], {%1,%2};" :: "r"(addr), "r"(a), "r"(b) : "memory");
}
__device__ __forceinline__ void sts64f(uint32_t addr, float a, float b) {
    asm volatile("st.shared.v2.b32 [%0], {%1,%2};" :: "r"(addr), "f"(a), "f"(b) : "memory");
}
__device__ __forceinline__ float2 lds64f(uint32_t addr) {
    float2 v;
    asm volatile("ld.shared.v2.b32 {%0,%1}, [%2];" : "=f"(v.x), "=f"(v.y) : "r"(addr));
    return v;
}
__device__ __forceinline__ void cpa16(uint32_t dst, const __half* src) {
    asm volatile("cp.async.cg.shared.global [%0], [%1], 16;"
                 :: "r"(dst), "l"(__cvta_generic_to_global(src)) : "memory");
}
#define CP_MBAR_ARRIVE(a) \
    asm volatile("cp.async.mbarrier.arrive.noinc.shared.b64 [%0];" :: "r"(a) : "memory")
#define MBAR_INIT(a, c) \
    asm volatile("mbarrier.init.shared.b64 [%0], %1;" :: "r"(a), "r"(c) : "memory")
#define MBAR_ARRIVE(a) \
    asm volatile("mbarrier.arrive.shared.b64 _, [%0];" :: "r"(a) : "memory")
#define MBAR_WAIT(addr, parity) do {                                                   \
    uint32_t _m = (addr), _p = (parity), _d;                                           \
    asm volatile("{.reg .pred p; mbarrier.try_wait.parity.acquire.cta.shared::cta.b64" \
                 " p, [%1], %2; selp.b32 %0,1,0,p;}"                                   \
                 : "=r"(_d) : "r"(_m), "r"(_p) : "memory");                            \
    if (!_d) {                                                                         \
        asm volatile("{.reg .pred P1;\n"                                               \
            "W_%=: mbarrier.try_wait.parity.acquire.cta.shared::cta.b64 P1,[%0],%1,0x989680;\n" \
            "@P1 bra.uni D_%=; bra.uni W_%=; D_%=:}\n"                                 \
            :: "r"(_m), "r"(_p) : "memory");                                           \
    }                                                                                  \
} while (0)

// 512 threads fill a 64x128(h) K/V tile pair: thread = one row (tid>>3) x 2 chunks
__device__ __forceinline__ void issue_kv(uint32_t sbk, uint32_t sbv,
                                         const __half* kg, const __half* vg, int tid)
{
    const int row = tid >> 3;
    const int cg  = (tid & 7) * 2;
    const uint32_t rbase = row * 256;
    const uint32_t key   = (row & 7);
    const __half* ks = kg + row * DH + cg * 8;
    const __half* vs = vg + row * DH + cg * 8;
    #pragma unroll
    for (int c2 = 0; c2 < 2; c2++) {
        const uint32_t sw = rbase + (((cg + c2) ^ key) << 4);
        cpa16(sbk + sw, ks + c2 * 8);
        cpa16(sbv + sw, vs + c2 * 8);
    }
}

__global__ void __launch_bounds__(NTHREADS, 1)
attn_fused_kernel(const float* __restrict__ Q, const float* __restrict__ K,
                  const float* __restrict__ V, const int* __restrict__ lens,
                  float* __restrict__ O, int T, int nq, int ntiles, int total4, int B)
{
    extern __shared__ __align__(1024) char smem[];
    const uint32_t sb = smem_u32(smem);
    volatile unsigned int* tslot = reinterpret_cast<unsigned int*>(smem + SM_TILE);
    int* ord = reinterpret_cast<int*>(smem + SM_ORD);

    const int tid  = threadIdx.x;
    const int lane = tid & 31;
    const int warp = tid >> 5;
    const int strip = warp & 7;          // row strip (16 rows)
    const int half  = warp >> 3;         // key half (32 of 64 keys per block)
    const int g = lane >> 2;
    const int r = lane & 3;

    // ===== phase 1: fp32 -> fp16 K/V (length-gated) =====
    {
        const int rowsz = DH / 4;                       // 32 float4 per row
        for (int i = blockIdx.x * NTHREADS + tid; i < total4; i += GRID_P * NTHREADS) {
            const int b = i / (T * rowsz);
            const int t = (i / rowsz) % T;
            if (t < ((lens[b] + 63) & ~63)) {
                float4 k = reinterpret_cast<const float4*>(K)[i];
                float4 v = reinterpret_cast<const float4*>(V)[i];
                reinterpret_cast<uint2*>(g_kh)[i] = make_uint2(pack2(k.x, k.y), pack2(k.z, k.w));
                reinterpret_cast<uint2*>(g_vh)[i] = make_uint2(pack2(v.x, v.y), pack2(v.z, v.w));
            }
        }
    }

    // ===== LPT order: rank batches by descending L (stable) =====
    if (tid < B && B <= 64) {
        const int Lb = lens[tid];
        int rank = 0;
        for (int j = 0; j < B; j++) {
            const int Lj = lens[j];
            rank += (Lj > Lb) || (Lj == Lb && j < tid);
        }
        ord[rank] = tid;
    }

    // ===== grid barrier (monotonic, graph-replay-safe) =====
    __threadfence();
    __syncthreads();
    if (tid == 0) {
        unsigned a = atomicAdd(&g_arrive, 1u) + 1u;
        unsigned target = ((a + GRID_P - 1u) / GRID_P) * GRID_P;
        unsigned v;
        do {
            asm volatile("ld.acquire.gpu.u32 %0, [%1];" : "=r"(v) : "l"(&g_arrive) : "memory");
        } while (v < target);
        *tslot = target / GRID_P - 1u;                  // 0-based launch index
    }
    __syncthreads();
    const unsigned tbase = (*tslot) * (unsigned)(ntiles + GRID_P);

    // ===== phase 2: persistent attention (R16 core, scheduler-friendly body) =====
    const uint32_t la = lane & 7;
    const uint32_t ls = (lane >> 3) & 1;
    const uint32_t lc = lane >> 4;
    const uint32_t arow = strip * 16 + la + ls * 8;
    const uint32_t qbase_sm = sb + SM_Q + arow * 256;

    const float QSC = 1.4426950408889634f / 256.0f;   // log2e / (d/0.5)
    const uint32_t ONES = pack2(1.f, 1.f);

    for (;;) {
        __syncthreads();                 // all warps done with prev tile smem/barriers
        if (tid == 0) {
            *tslot = atomicAdd(&g_ticket, 1u) - tbase;
            MBAR_INIT(sb + SM_FULL + 0, NTHREADS);
            MBAR_INIT(sb + SM_FULL + 8, NTHREADS);
            MBAR_INIT(sb + SM_FREE + 0, NTHREADS);
            MBAR_INIT(sb + SM_FREE + 8, NTHREADS);
        }
        __syncthreads();
        const unsigned int t = *tslot;
        if (t >= (unsigned)ntiles) return;

        const int b     = ord[t / (unsigned)nq];        // LPT: longest batches first
        const int qbase = (int)(t % (unsigned)nq) * BM;
        const int L     = lens[b];
        float* Ob = O + ((size_t)b * T + qbase) * DH;

        if (L <= 0) {
            const float4 z = make_float4(0.f, 0.f, 0.f, 0.f);
            for (int i = tid; i < BM * DH / 4; i += NTHREADS)
                reinterpret_cast<float4*>(Ob)[i] = z;
            continue;
        }

        const int nblk = (L + BN - 1) >> 6;
        const __half* kg = g_kh + ((size_t)b * T) * DH;
        const __half* vg = g_vh + ((size_t)b * T) * DH;

        // prologue: fill stage 0 with block 0
        issue_kv(sb + SM_K0, sb + SM_V0, kg, vg, tid);
        CP_MBAR_ARRIVE(sb + SM_FULL + 0);

        // ---- Q tile: each warp stages 8 rows (strip*16 + half*8 + rr) ----
        const float* Qg = Q + ((size_t)b * T + qbase) * DH;
        {
            const uint32_t c   = lane >> 1;
            const uint32_t off = (lane & 1) * 8;
            #pragma unroll
            for (int rr = 0; rr < 8; rr++) {
                const int row = strip * 16 + half * 8 + rr;
                float4 v = reinterpret_cast<const float4*>(Qg + (size_t)row * DH)[lane];
                uint32_t a = sb + SM_Q + row * 256 + ((c ^ (row & 7)) << 4) + off;
                sts64(a, pack2(v.x * QSC, v.y * QSC), pack2(v.z * QSC, v.w * QSC));
            }
        }
        __syncthreads();                 // Q visible; keep producer convoyed (R9 lesson)

        float oacc[16][4];
        #pragma unroll
        for (int nt = 0; nt < 16; nt++)
            #pragma unroll
            for (int i = 0; i < 4; i++) oacc[nt][i] = 0.f;
        float rsum[4] = {0.f, 0.f, 0.f, 0.f};

        for (int kb = 0; kb < nblk; kb++) {
            const int s0 = kb & 1;
            const uint32_t kbuf = sb + (s0 ? SM_K1 : SM_K0);
            const uint32_t vbuf = sb + (s0 ? SM_V1 : SM_V0);

            if (kb + 1 < nblk) {
                const int s1 = s0 ^ 1;
                const int n = (kb + 1) >> 1;
                if (n > 0) MBAR_WAIT(sb + SM_FREE + s1 * 8, (n - 1) & 1);
                issue_kv(sb + (s1 ? SM_K1 : SM_K0), sb + (s1 ? SM_V1 : SM_V0),
                         kg + (size_t)(kb + 1) * BN * DH,
                         vg + (size_t)(kb + 1) * BN * DH, tid);
                CP_MBAR_ARRIVE(sb + SM_FULL + s1 * 8);
            }

            MBAR_WAIT(sb + SM_FULL + s0 * 8, (kb >> 1) & 1);

            // ---- S = Q K^T : this warp's 16 rows x its 32 keys ----
            float sacc[4][4];
            #pragma unroll
            for (int nt = 0; nt < 4; nt++)
                #pragma unroll
                for (int i = 0; i < 4; i++) sacc[nt][i] = 0.f;

            #pragma unroll
            for (int kt = 0; kt < 8; kt++) {
                const uint32_t xo = (((2 * kt + lc) ^ la) << 4);
                uint32_t a[4];
                ldsm_x4(a, qbase_sm + xo);
                #pragma unroll
                for (int ng = 0; ng < 2; ng++) {
                    uint32_t bb[4];
                    ldsm_x4(bb, kbuf + (half * 32 + ng * 16 + la + ls * 8) * 256 + xo);
                    mma16816(sacc[ng * 2    ], a, bb[0], bb[2]);
                    mma16816(sacc[ng * 2 + 1], a, bb[1], bb[3]);
                }
            }

            // ---- exp + PV interleaved per kc: exp(pa[kc]) just before its MMAs,
            //      non-volatile MMAs let ptxas overlap the next kc's MUFU chain ----
            const int kcb = kb * BN + half * 32;
            const bool full = (kcb + 32 <= L);
            #pragma unroll
            for (int kc = 0; kc < 2; kc++) {
                uint32_t pa[4];
                if (full) {
                    pa[0] = ex2h2(pack2(sacc[2*kc  ][0], sacc[2*kc  ][1]));
                    pa[1] = ex2h2(pack2(sacc[2*kc  ][2], sacc[2*kc  ][3]));
                    pa[2] = ex2h2(pack2(sacc[2*kc+1][0], sacc[2*kc+1][1]));
                    pa[3] = ex2h2(pack2(sacc[2*kc+1][2], sacc[2*kc+1][3]));
                } else {
                    #pragma unroll
                    for (int j = 0; j < 2; j++) {
                        const int nt = 2 * kc + j;
                        const int col = kcb + nt * 8 + 2 * r;
                        float p0 = (col     < L) ? ex2f(sacc[nt][0]) : 0.f;
                        float p1 = (col + 1 < L) ? ex2f(sacc[nt][1]) : 0.f;
                        float p2 = (col     < L) ? ex2f(sacc[nt][2]) : 0.f;
                        float p3 = (col + 1 < L) ? ex2f(sacc[nt][3]) : 0.f;
                        pa[2*j    ] = pack2(p0, p1);
                        pa[2*j + 1] = pack2(p2, p3);
                    }
                }

                mma16816(rsum, pa, ONES, ONES);
                const uint32_t vrow = (half * 32 + kc * 16 + la + ls * 8) * 256;
                #pragma unroll
                for (int ng = 0; ng < 8; ng++) {
                    uint32_t bb[4];
                    ldsm_x4t(bb, vbuf + vrow + (((2 * ng + lc) ^ la) << 4));
                    mma16816(oacc[ng * 2    ], pa, bb[0], bb[1]);
                    mma16816(oacc[ng * 2 + 1], pa, bb[2], bb[3]);
                }
            }

            MBAR_ARRIVE(sb + SM_FREE + s0 * 8);
        }

        // ---- pair combine: half1 publishes partials, half0 merges + stores ----
        __syncthreads();                  // all reads of tile buffers done
        if (half == 1) {
            const uint32_t xo = sb + SM_XO + strip * 8192;
            #pragma unroll
            for (int nt = 0; nt < 16; nt++) {
                const uint32_t cb = nt * 32 + r * 8;
                sts64f(xo + g * 512 + cb,        oacc[nt][0], oacc[nt][1]);
                sts64f(xo + (g + 8) * 512 + cb,  oacc[nt][2], oacc[nt][3]);
            }
            if (r == 0) {
                *reinterpret_cast<float*>(smem + SM_XR + (strip * 16 + g) * 4)     = rsum[0];
                *reinterpret_cast<float*>(smem + SM_XR + (strip * 16 + 8 + g) * 4) = rsum[2];
            }
        }
        __syncthreads();
        if (half == 0) {
            const float* rsx = reinterpret_cast<const float*>(smem + SM_XR);
            const float inv0 = 1.0f / (rsum[0] + rsx[strip * 16 + g]);
            const float inv1 = 1.0f / (rsum[2] + rsx[strip * 16 + 8 + g]);
            const uint32_t xo = sb + SM_XO + strip * 8192;
            const int row0 = strip * 16 + g;
            #pragma unroll
            for (int nt = 0; nt < 16; nt++) {
                const int col = nt * 8 + 2 * r;
                const uint32_t cb = nt * 32 + r * 8;
                float2 x0 = lds64f(xo + g * 512 + cb);
                float2 x1 = lds64f(xo + (g + 8) * 512 + cb);
                *reinterpret_cast<float2*>(Ob + (size_t)row0 * DH + col) =
                    make_float2((oacc[nt][0] + x0.x) * inv0, (oacc[nt][1] + x0.y) * inv0);
                *reinterpret_cast<float2*>(Ob + (size_t)(row0 + 8) * DH + col) =
                    make_float2((oacc[nt][2] + x1.x) * inv1, (oacc[nt][3] + x1.y) * inv1);
            }
        }
    }
}

extern "C" void kernel_launch(void* const* d_in, const int* in_sizes, int n_in,
                              void* d_out, int out_size)
{
    const float* Q    = (const float*)d_in[0];
    const float* K    = (const float*)d_in[1];
    const float* V    = (const float*)d_in[2];
    const int*   lens = (const int*)d_in[3];
    float* O = (float*)d_out;

    const int B = in_sizes[3];
    const int T = in_sizes[0] / (B * DH);
    const int nq = T / BM;
    const int ntiles = nq * B;
    const int total4 = in_sizes[1] / 4;   // B*T*32 float4 per tensor

    cudaFuncSetAttribute(attn_fused_kernel,
                         cudaFuncAttributeMaxDynamicSharedMemorySize, SM_TOTAL);
    attn_fused_kernel<<<GRID_P, NTHREADS, SM_TOTAL>>>(Q, K, V, lens, O,
                                                      T, nq, ntiles, total4, B);
}